// round 6
// baseline (speedup 1.0000x reference)
#include <cuda_runtime.h>
#include <math.h>

// Problem shape (fixed by setup_inputs): B=8, Sq=Sk=1024, D=64, N_QUBITS=4.
#define B_     8
#define SQ_    1024
#define SK_    1024
#define D_     64
#define NQ_    4
#define NROWS_ (B_ * SQ_)          // 8192 rows per side

// Raw per-row scratch (NO theta dependence):
//  q-side AoS [row][8]:  per qubit (0.5*sin(pi t), 0.5*cos(pi t))
//  k-side SoA [b][comp(8)][SK]: per qubit (sin(pi t), cos(pi t))
// Theta enters only through the per-qubit 2x2 Gram matrix G (16 scalars for
// the whole problem), computed once in prep and applied to the register
// k-tile in pair's prologue:
//   factor = 0.5 + q0*(G00 kS + G01 kC) + q1*(G10 kS + G11 kC)
__device__ float  g_q[NROWS_ * 8];
__device__ float  g_k[B_ * 8 * SK_];
__device__ float2 g_Gd[16];        // duplicated {g,g} pairs, [n*4 + i*2 + j]

// ---------------------------------------------------------------------------
// packed f32x2 helpers
// ---------------------------------------------------------------------------
__device__ __forceinline__ unsigned long long f2fma(unsigned long long a,
                                                    unsigned long long b,
                                                    unsigned long long c)
{
    unsigned long long d;
    asm("fma.rn.f32x2 %0, %1, %2, %3;" : "=l"(d) : "l"(a), "l"(b), "l"(c));
    return d;
}
__device__ __forceinline__ unsigned long long f2mul(unsigned long long a,
                                                    unsigned long long b)
{
    unsigned long long d;
    asm("mul.rn.f32x2 %0, %1, %2;" : "=l"(d) : "l"(a), "l"(b));
    return d;
}
__device__ __forceinline__ unsigned long long f2dup(float v)
{
    unsigned long long d;
    asm("mov.b64 %0, {%1, %1};" : "=l"(d) : "f"(v));
    return d;
}

#define HALF2_ 0x3F0000003F000000ULL   // {0.5f, 0.5f}

// Bloch-rotation columns of M = Rz(om)*Ry(th)*Rz(phi):  u = M*ex, v = M*ez
__device__ __forceinline__ void uv_cols(float phi, float th, float om,
                                        float u[3], float v[3])
{
    float sp, cp, st, ct, so, co;
    sincosf(phi, &sp, &cp);
    sincosf(th,  &st, &ct);
    sincosf(om,  &so, &co);
    float ax = ct * cp, ay = sp, az = -st * cp;
    u[0] = ax * co - ay * so;
    u[1] = ax * so + ay * co;
    u[2] = az;
    v[0] = st * co;
    v[1] = st * so;
    v[2] = ct;
}

// ---------------------------------------------------------------------------
// Phase 1: raw (S,C) per row; block 0 threads 0..15 also compute G.
// rows [0,8192) -> query side, [8192,16384) -> key side
// ---------------------------------------------------------------------------
__global__ void prep_kernel(const float* __restrict__ query,
                            const float* __restrict__ key,
                            const float* __restrict__ theta_q,
                            const float* __restrict__ theta_k)
{
    int tid = threadIdx.x;
    int row = blockIdx.x * blockDim.x + tid;

    // G: 16 redundant computations, one entry per thread
    if (blockIdx.x == 0 && tid < 16) {
        int n = tid >> 2, i = (tid >> 1) & 1, j = tid & 1;
        float uq[3], vq[3], uk[3], vk[3];
        uv_cols(theta_q[3 * n], theta_q[3 * n + 1], theta_q[3 * n + 2], uq, vq);
        uv_cols(theta_k[3 * n], theta_k[3 * n + 1], theta_k[3 * n + 2], uk, vk);
        const float* a  = i ? vq : uq;
        const float* bb = j ? vk : uk;
        float g = a[0] * bb[0] + a[1] * bb[1] + a[2] * bb[2];
        g_Gd[tid] = make_float2(g, g);
    }

    if (row >= 2 * NROWS_) return;

    bool isQ = row < NROWS_;
    int r = isQ ? row : row - NROWS_;

    // first 4 of the 64 features, 16B-aligned (row stride 256B)
    float4 xv = *(const float4*)((isQ ? query : key) + (size_t)r * D_);
    float xs[4] = {xv.x, xv.y, xv.z, xv.w};

    float S[NQ_], C[NQ_];
#pragma unroll
    for (int n = 0; n < NQ_; n++) {
        float t = tanhf(xs[n]);
        sincospif(t, &S[n], &C[n]);
    }

    if (isQ) {
        float out8[8];
#pragma unroll
        for (int n = 0; n < NQ_; n++) {
            out8[2 * n]     = 0.5f * S[n];
            out8[2 * n + 1] = 0.5f * C[n];
        }
        float* d = g_q + (size_t)r * 8;
        *(float4*)(d)     = *(const float4*)(out8);
        *(float4*)(d + 4) = *(const float4*)(out8 + 4);
    } else {
        int b = r >> 10;           // SK_ = 1024
        int s = r & (SK_ - 1);
#pragma unroll
        for (int n = 0; n < NQ_; n++) {
            g_k[((size_t)(b * 8 + 2 * n))     * SK_ + s] = S[n];
            g_k[((size_t)(b * 8 + 2 * n + 1)) * SK_ + s] = C[n];
        }
    }
}

// ---------------------------------------------------------------------------
// Phase 2: out[b][q][k] = 0.5 + 0.5 * prod_n (0.5 + q.(G k))
// Tile: 128 q x 128 k, 256 threads; thread owns 4 k-cols as packed pairs,
// iterates 16 q-rows.  q rows in smem UNduplicated (2 LDS.128/row, packed
// via mov.b64 on the ALU pipe).  4 blocks/SM -> whole grid in one wave.
// ---------------------------------------------------------------------------
#define TQ 128
#define TK 128

__global__ __launch_bounds__(256, 4) void pair_kernel(float* __restrict__ out)
{
    __shared__ __align__(16) float  sq[TQ][8];         // raw q rows
    __shared__ __align__(16) float4 skv[8][TK / 4];    // SoA raw k tile

    int b  = blockIdx.z;
    int q0 = blockIdx.y * TQ;
    int k0 = blockIdx.x * TK;
    int tid = threadIdx.x;

    // fill skv: 8 comps * 32 float4 = 256 float4 -> one per thread
    {
        int comp = tid >> 5, off = tid & 31;
        skv[comp][off] =
            *(const float4*)(g_k + ((size_t)(b * 8 + comp)) * SK_ + k0 + off * 4);
    }
    // fill sq: TQ*8 floats = 256 float4 -> one per thread
    ((float4*)sq)[tid] =
        ((const float4*)(g_q + (size_t)(b * SQ_ + q0) * 8))[tid];
    __syncthreads();

    int k4 = tid & 31;     // this thread's 4 consecutive k columns
    int qg = tid >> 5;     // q group: rows qg*16 .. qg*16+15

    // raw k tile -> registers, then apply G once (32 packed ops)
    ulonglong2 kd[8];
#pragma unroll
    for (int j = 0; j < 8; j++)
        kd[j] = *(const ulonglong2*)&skv[j][k4];

#pragma unroll
    for (int n = 0; n < NQ_; n++) {
        unsigned long long g00 = *(const unsigned long long*)&g_Gd[n * 4 + 0];
        unsigned long long g01 = *(const unsigned long long*)&g_Gd[n * 4 + 1];
        unsigned long long g10 = *(const unsigned long long*)&g_Gd[n * 4 + 2];
        unsigned long long g11 = *(const unsigned long long*)&g_Gd[n * 4 + 3];
        ulonglong2 S = kd[2 * n], C = kd[2 * n + 1];
        kd[2 * n].x     = f2fma(g00, S.x, f2mul(g01, C.x));
        kd[2 * n].y     = f2fma(g00, S.y, f2mul(g01, C.y));
        kd[2 * n + 1].x = f2fma(g10, S.x, f2mul(g11, C.x));
        kd[2 * n + 1].y = f2fma(g10, S.y, f2mul(g11, C.y));
    }

    float* obase = out + ((size_t)(b * SQ_ + q0 + qg * 16) * SK_) + k0 + k4 * 4;

#pragma unroll
    for (int r = 0; r < 16; r++) {
        // 2 LDS.128 (warp-uniform broadcast) + 8 ALU packs
        float4 v0 = *(const float4*)&sq[qg * 16 + r][0];
        float4 v1 = *(const float4*)&sq[qg * 16 + r][4];
        unsigned long long qd[8];
        qd[0] = f2dup(v0.x); qd[1] = f2dup(v0.y);
        qd[2] = f2dup(v0.z); qd[3] = f2dup(v0.w);
        qd[4] = f2dup(v1.x); qd[5] = f2dup(v1.y);
        qd[6] = f2dup(v1.z); qd[7] = f2dup(v1.w);

        unsigned long long t0[NQ_], t1[NQ_];
#pragma unroll
        for (int n = 0; n < NQ_; n++) {
            t0[n] = f2fma(qd[2 * n], kd[2 * n].x,
                    f2fma(qd[2 * n + 1], kd[2 * n + 1].x, HALF2_));
            t1[n] = f2fma(qd[2 * n], kd[2 * n].y,
                    f2fma(qd[2 * n + 1], kd[2 * n + 1].y, HALF2_));
        }
        unsigned long long p0 = f2mul(f2mul(t0[0], t0[1]), f2mul(t0[2], t0[3]));
        unsigned long long p1 = f2mul(f2mul(t1[0], t1[1]), f2mul(t1[2], t1[3]));
        p0 = f2fma(p0, HALF2_, HALF2_);
        p1 = f2fma(p1, HALF2_, HALF2_);

        asm volatile("st.global.v2.b64 [%0], {%1, %2};"
                     :: "l"(obase + (size_t)r * SK_), "l"(p0), "l"(p1)
                     : "memory");
    }
}

extern "C" void kernel_launch(void* const* d_in, const int* in_sizes, int n_in,
                              void* d_out, int out_size)
{
    const float* query   = (const float*)d_in[0];
    const float* key     = (const float*)d_in[1];
    const float* theta_q = (const float*)d_in[2];
    const float* theta_k = (const float*)d_in[3];
    float* out = (float*)d_out;

    prep_kernel<<<(2 * NROWS_ + 255) / 256, 256>>>(query, key, theta_q, theta_k);

    dim3 grid(SK_ / TK, SQ_ / TQ, B_);
    pair_kernel<<<grid, 256>>>(out);
}